// round 12
// baseline (speedup 1.0000x reference)
#include <cuda_runtime.h>
#include <cuda_fp16.h>
#include <cstdint>

#define BB    16
#define CC    512
#define NPOS  400
#define HID   256
#define NEMB  30
#define TT    201
#define OUTW  38
#define RCL   8
#define NLOC  50
#define NTHR  1024
#define FSTR2 520       // padded feat row stride (halves)

// ---------------- device scratch ----------------
__device__ float  g_i2h4[CC * HID];      // [c/4][h][4] interleaved fp32
__device__ float  g_Wcomb[OUTW * HID];   // fused output heads
__device__ float  g_bcomb[OUTW];
__device__ float  g_h2hT[HID * HID];     // h2h transposed: [j][i]
__device__ __half g_wihH[3 * HID * 512]; // wih ctx part, fp16
__device__ float  g_wihEB[3 * HID * 32]; // wih emb cols + bih folded, fp32
__device__ __half g_whhH[3 * HID * HID]; // whh, fp16

// ---------------- helpers ----------------
__device__ __forceinline__ uint32_t smem_u32(const void* p) {
    return (uint32_t)__cvta_generic_to_shared(p);
}
__device__ __forceinline__ uint32_t mapa_u32(uint32_t addr, uint32_t rank) {
    uint32_t r;
    asm("mapa.shared::cluster.u32 %0, %1, %2;" : "=r"(r) : "r"(addr), "r"(rank));
    return r;
}
__device__ __forceinline__ float ld_dsm(uint32_t a) {
    float v;
    asm volatile("ld.shared::cluster.f32 %0, [%1];" : "=f"(v) : "r"(a));
    return v;
}
__device__ __forceinline__ uint32_t ld_dsm_u32(uint32_t a) {
    uint32_t v;
    asm volatile("ld.shared::cluster.b32 %0, [%1];" : "=r"(v) : "r"(a));
    return v;
}
__device__ __forceinline__ float2 ld_dsm_v2(uint32_t a) {
    float2 v;
    asm volatile("ld.shared::cluster.v2.f32 {%0, %1}, [%2];"
                 : "=f"(v.x), "=f"(v.y) : "r"(a));
    return v;
}
__device__ __forceinline__ void st_dsm(uint32_t a, float v) {
    asm volatile("st.shared::cluster.f32 [%0], %1;" :: "r"(a), "f"(v));
}
#define CLUSTER_SYNC() do { \
    asm volatile("barrier.cluster.arrive.aligned;" ::: "memory"); \
    asm volatile("barrier.cluster.wait.aligned;"   ::: "memory"); } while (0)
#define BAR1_768() asm volatile("bar.sync 1, 768;" ::: "memory")

__device__ __forceinline__ float sigmoidf_(float x) {
    return __fdividef(1.f, 1.f + __expf(-x));
}
__device__ __forceinline__ float tanh_acc(float x) {
    float cx = fminf(fmaxf(x, -15.f), 15.f);
    float e = __expf(2.f * cx);
    return __fdividef(e - 1.f, e + 1.f);
}
__device__ __forceinline__ __half2 tanh2(__half2 x) {   // HW f16x2 tanh
    uint32_t u = *reinterpret_cast<uint32_t*>(&x);
    asm("tanh.approx.f16x2 %0, %0;" : "+r"(u));
    return *reinterpret_cast<__half2*>(&u);
}
__device__ __forceinline__ float4 f4(const float* p) { return *(const float4*)p; }
__device__ __forceinline__ float2 f2(const float* p) { return *(const float2*)p; }
__device__ __forceinline__ float4 ldsh4(const __half* p) {   // 4 halves -> 4 floats
    uint2 u = *reinterpret_cast<const uint2*>(p);
    float2 a = __half22float2(*reinterpret_cast<half2*>(&u.x));
    float2 b = __half22float2(*reinterpret_cast<half2*>(&u.y));
    return make_float4(a.x, a.y, b.x, b.y);
}

// ---------------- prep kernel ----------------
__global__ void prep_kernel(const float* __restrict__ i2h, const float* __restrict__ h2h_w,
                            const float* __restrict__ wih, const float* __restrict__ bih,
                            const float* __restrict__ whh,
                            const float* __restrict__ sg1w, const float* __restrict__ sg1b,
                            const float* __restrict__ sg2w, const float* __restrict__ sg2b,
                            const float* __restrict__ lg1w, const float* __restrict__ lg1b,
                            const float* __restrict__ lg2w, const float* __restrict__ lg2b) {
    int blk = blockIdx.x, tid = threadIdx.x;
    if (blk < OUTW) {
        const float *W2, *W1, *b1, *b2; int row;
        if (blk < NEMB) { row = blk;        W2 = sg2w; W1 = sg1w; b1 = sg1b; b2 = sg2b; }
        else            { row = blk - NEMB; W2 = lg2w; W1 = lg1w; b1 = lg1b; b2 = lg2b; }
        float acc = 0.f;
        for (int k = 0; k < HID; k++) acc += W2[row * HID + k] * W1[k * HID + tid];
        g_Wcomb[blk * HID + tid] = acc;
        __shared__ float red[HID];
        red[tid] = W2[row * HID + tid] * b1[tid];
        __syncthreads();
        for (int s = HID / 2; s > 0; s >>= 1) {
            if (tid < s) red[tid] += red[tid + s];
            __syncthreads();
        }
        if (tid == 0) g_bcomb[blk] = red[0] + b2[row];
    } else if (blk < OUTW + CC) {
        int c = blk - OUTW;
        g_i2h4[(c >> 2) * HID * 4 + tid * 4 + (c & 3)] = i2h[tid * CC + c];
    } else if (blk < OUTW + CC + HID) {
        int j = blk - OUTW - CC;
        g_h2hT[j * HID + tid] = h2h_w[tid * HID + j];
    } else {
        int m = blk - OUTW - CC - HID;           // 0..767
        for (int c = tid; c < 512; c += HID)
            g_wihH[m * 512 + c] = __float2half_rn(wih[m * 542 + c]);
        if (tid < NEMB)
            g_wihEB[m * 32 + tid] = wih[m * 542 + 512 + tid] + bih[m];
        else if (tid < 32)
            g_wihEB[m * 32 + tid] = 0.f;
        g_whhH[m * HID + tid] = __float2half_rn(whh[m * HID + tid]);
    }
}

// ---------------- shared memory ----------------
struct __align__(16) Smem {
    __half  featH[NLOC * FSTR2]; // local feat slice, fp16  (52000 B)
    __half  hproj[NLOC * HID];   // i2h(feat) slice, fp16   (25600 B)
    __half  wihS[96 * 512];      // GRU wih slice, fp16     (98304 B)
    float   h2hs[32 * HID];      // h2hT slice, fp32        (32768 B)
    float   pp[HID];
    float   pp_part[HID];
    float   pp2[2][HID];         // k-split pp partials
    __half2 pctx3[3][256];       // row-group ctx partials
    __half2 pctxH[256];          // final partial ctx, half2
    float   ctxS[516];           // reduced ctx fp32 (+ expsum at [512])
    float   h2hb[HID];
    float   hid[2][HID];
    float   gh[96];
    float   hloc[32];
    float   wexp[64];
    float   esloc;               // local expsum
    int     schars[224];
    float   pad[3];
};

// ---------------- main persistent cluster kernel ----------------
__global__ void __launch_bounds__(NTHR, 1) __cluster_dims__(RCL, 1, 1)
sla_kernel(const float* __restrict__ fea, const int* __restrict__ structure,
           const float* __restrict__ h2h_b, const float* __restrict__ score_w,
           const float* __restrict__ bhh,
           float* __restrict__ out) {
    extern __shared__ char smem_raw[];
    Smem* sm = (Smem*)smem_raw;
    const int tid  = threadIdx.x;
    const int lane = tid & 31;
    const int wid  = tid >> 5;
    const int b    = blockIdx.x >> 3;
    const int r    = blockIdx.x & 7;

    // ---- prologue: feat (fp16), wih slice (fp16), h2hT slice, biases ----
    {
        const float* fb = fea + (size_t)b * CC * NPOS;
        for (int idx = tid; idx < NLOC * CC; idx += NTHR) {
            int c  = idx / NLOC;
            int nl = idx - c * NLOC;
            sm->featH[nl * FSTR2 + c] = __float2half_rn(fb[c * NPOS + r * NLOC + nl]);
        }
        for (int i = tid; i < 96 * 512 / 8; i += NTHR) {
            int le = i * 8;
            int lr = le >> 9;                  // local row 0..95
            int cc = le & 511;
            int m  = (lr >> 5) * 256 + r * 32 + (lr & 31);
            reinterpret_cast<uint4*>(sm->wihS)[i] =
                reinterpret_cast<const uint4*>(g_wihH)[(m * 512 + cc) >> 3];
        }
        for (int i = tid; i < 32 * HID; i += NTHR)
            sm->h2hs[i] = g_h2hT[(size_t)(r * 32) * HID + i];
        for (int i = tid; i < HID; i += NTHR) {
            sm->h2hb[i]    = h2h_b[i];
            sm->hid[0][i]  = 0.f;
            sm->hid[1][i]  = 0.f;
            sm->pp_part[i] = 0.f;
        }
        if (tid < TT) sm->schars[tid] = structure[b * TT + tid];
        if (tid >= TT && tid < 224) sm->schars[tid] = 0;
    }
    __syncthreads();

    // ---- prologue: hproj[nl][h] = sum_c feat[nl][c] * i2h[h][c] (fp16 out) ----
    {
        int h  = tid & 255;
        int g  = tid >> 8;            // 0..3
        int n0 = g * 13;
        float acc[13];
        #pragma unroll
        for (int i = 0; i < 13; i++) acc[i] = 0.f;
        for (int cb = 0; cb < CC / 4; cb++) {
            float4 w = f4(&g_i2h4[cb * HID * 4 + h * 4]);
            #pragma unroll
            for (int i = 0; i < 13; i++) {
                int n = n0 + i;
                if (n < NLOC) {
                    float4 fv = ldsh4(&sm->featH[n * FSTR2 + cb * 4]);
                    acc[i] += fv.x * w.x + fv.y * w.y + fv.z * w.z + fv.w * w.w;
                }
            }
        }
        #pragma unroll
        for (int i = 0; i < 13; i++) {
            int n = n0 + i;
            if (n < NLOC) sm->hproj[n * HID + h] = __float2half_rn(acc[i]);
        }
    }

    // persistent score regs (half2) for attention warps
    __half2 sv2[4];
    if (wid < 24) {
        float4 s0 = f4(&score_w[lane * 8]);
        float4 s1 = f4(&score_w[lane * 8 + 4]);
        sv2[0] = __floats2half2_rn(s0.x, s0.y);
        sv2[1] = __floats2half2_rn(s0.z, s0.w);
        sv2[2] = __floats2half2_rn(s1.x, s1.y);
        sv2[3] = __floats2half2_rn(s1.z, s1.w);
    }
    CLUSTER_SYNC();

    // ---- decode loop (t == TT is the output-only epilogue) ----
    for (int t = 0; t <= TT; t++) {
        const int cur = t & 1, nxt = cur ^ 1;

        // ================= PHASE A =================
        if (wid >= 24) {
            float4 h0 = f4(&sm->hid[cur][lane * 8]);
            float4 h1 = f4(&sm->hid[cur][lane * 8 + 4]);
            if (t < TT) {
                // gh = whh @ h + bhh (12 gate-rows per warp), fp16 weights
                #pragma unroll 4
                for (int i = 0; i < 12; i++) {
                    int m2 = (wid - 24) * 12 + i;     // 0..95
                    int g  = m2 >> 5, u = m2 & 31;
                    const __half* wr = g_whhH + (size_t)(g * HID + r * 32 + u) * HID + lane * 8;
                    uint4 u4 = *reinterpret_cast<const uint4*>(wr);
                    half2* hh = reinterpret_cast<half2*>(&u4);
                    float2 w0 = __half22float2(hh[0]);
                    float2 w1 = __half22float2(hh[1]);
                    float2 w2 = __half22float2(hh[2]);
                    float2 w3 = __half22float2(hh[3]);
                    float a = w0.x * h0.x + w0.y * h0.y + w1.x * h0.z + w1.y * h0.w
                            + w2.x * h1.x + w2.y * h1.y + w3.x * h1.z + w3.y * h1.w;
                    #pragma unroll
                    for (int o = 16; o > 0; o >>= 1) a += __shfl_xor_sync(0xffffffffu, a, o);
                    if (lane == 0) sm->gh[m2] = a + bhh[g * HID + r * 32 + u];
                }
            }
            if (t > 0 && wid < 29) {
                int ow = r + 8 * (wid - 24);
                if (ow < OUTW) {
                    const float* wr = g_Wcomb + ow * HID + lane * 8;
                    float4 w0 = f4(wr), w1 = f4(wr + 4);
                    float a = w0.x * h0.x + w0.y * h0.y + w0.z * h0.z + w0.w * h0.w
                            + w1.x * h1.x + w1.y * h1.y + w1.z * h1.z + w1.w * h1.w;
                    #pragma unroll
                    for (int o = 16; o > 0; o >>= 1) a += __shfl_xor_sync(0xffffffffu, a, o);
                    if (lane == 0) {
                        a += g_bcomb[ow];
                        if (ow >= NEMB) a = sigmoidf_(a);
                        out[((size_t)b * TT + (t - 1)) * OUTW + ow] = a;
                    }
                }
            }
        } else if (t < TT) {
            // pp assemble: 128 threads, float2 remote pulls + bias
            if (tid < 128) {
                uint32_t base = smem_u32(&sm->pp_part[tid * 2]);
                float2 acc = f2(&sm->h2hb[tid * 2]);
                #pragma unroll
                for (int p = 0; p < RCL; p++) {
                    float2 v = ld_dsm_v2(mapa_u32(base, p));
                    acc.x += v.x; acc.y += v.y;
                }
                *(float2*)&sm->pp[tid * 2] = acc;
            }
            BAR1_768();
            // attention: rows 2*wid, 2*wid+1 (+48+wid for wid<2); f16x2 tanh + dot
            {
                float4 pv0 = f4(&sm->pp[lane * 8]);
                float4 pv1 = f4(&sm->pp[lane * 8 + 4]);
                __half2 pv2[4];
                pv2[0] = __floats2half2_rn(pv0.x, pv0.y);
                pv2[1] = __floats2half2_rn(pv0.z, pv0.w);
                pv2[2] = __floats2half2_rn(pv1.x, pv1.y);
                pv2[3] = __floats2half2_rn(pv1.z, pv1.w);
                int rows[3]; int nr = 2;
                rows[0] = 2 * wid; rows[1] = 2 * wid + 1;
                if (wid < 2) { rows[2] = 48 + wid; nr = 3; }
                for (int q = 0; q < nr; q++) {
                    int n = rows[q];
                    uint4 u = *reinterpret_cast<const uint4*>(&sm->hproj[n * HID + lane * 8]);
                    half2* hh = reinterpret_cast<half2*>(&u);
                    __half2 m0 = __hmul2(tanh2(__hadd2(hh[0], pv2[0])), sv2[0]);
                    __half2 m1 = __hmul2(tanh2(__hadd2(hh[1], pv2[1])), sv2[1]);
                    __half2 m2 = __hmul2(tanh2(__hadd2(hh[2], pv2[2])), sv2[2]);
                    __half2 m3 = __hmul2(tanh2(__hadd2(hh[3], pv2[3])), sv2[3]);
                    __half2 s2 = __hadd2(__hadd2(m0, m1), __hadd2(m2, m3));
                    float2 fs = __half22float2(s2);
                    float a = fs.x + fs.y;
                    #pragma unroll
                    for (int o = 16; o > 0; o >>= 1) a += __shfl_xor_sync(0xffffffffu, a, o);
                    if (lane == 0) sm->wexp[n] = __expf(a);
                }
            }
            BAR1_768();
            // partial context: all 24 warps, 3 row-groups (17/17/16)
            {
                int grp = wid >> 3;              // 0..2
                int ch  = tid & 255;             // half2 channel
                int n0g = grp * 17;
                int n1g = (grp == 2) ? 50 : n0g + 17;
                const half2* fp2 = reinterpret_cast<const half2*>(sm->featH);
                float2 a = make_float2(0.f, 0.f);
                for (int n = n0g; n < n1g; n++) {
                    float w = sm->wexp[n];
                    float2 fv = __half22float2(fp2[n * (FSTR2 / 2) + ch]);
                    a.x += w * fv.x; a.y += w * fv.y;
                }
                sm->pctx3[grp][ch] = __floats2half2_rn(a.x, a.y);
            }
            BAR1_768();
            if (tid < 256) {                 // combine 3 partials -> pctxH
                sm->pctxH[tid] = __hadd2(__hadd2(sm->pctx3[0][tid], sm->pctx3[1][tid]),
                                         sm->pctx3[2][tid]);
            }
            if (wid == 8) {                  // local expsum -> esloc
                float v = (lane < 25) ? sm->wexp[lane] + sm->wexp[lane + 25] : 0.f;
                #pragma unroll
                for (int o = 16; o > 0; o >>= 1) v += __shfl_xor_sync(0xffffffffu, v, o);
                if (lane == 0) sm->esloc = v;
            }
        }
        if (t == TT) break;

        CLUSTER_SYNC();   // S1: pctxH/esloc + gh ready

        // ================= PHASE B =================
        // ctx all-reduce: 8 warps pull half2 partials from 8 peers, sum fp32
        if (tid < 256) {
            uint32_t base = smem_u32(&sm->pctxH[tid]);
            float ax = 0.f, ay = 0.f;
            #pragma unroll
            for (int p = 0; p < RCL; p++) {
                uint32_t raw = ld_dsm_u32(mapa_u32(base, p));
                float2 f = __half22float2(*reinterpret_cast<half2*>(&raw));
                ax += f.x; ay += f.y;
            }
            *(float2*)&sm->ctxS[tid * 2] = make_float2(ax, ay);
        }
        if (wid == 8) {              // expsum all-reduce
            float e = (lane < RCL) ? ld_dsm(mapa_u32(smem_u32(&sm->esloc), lane)) : 0.f;
            e += __shfl_xor_sync(0xffffffffu, e, 1);
            e += __shfl_xor_sync(0xffffffffu, e, 2);
            e += __shfl_xor_sync(0xffffffffu, e, 4);
            if (lane == 0) sm->ctxS[512] = e;
        }
        __syncthreads();

        // GRU input GEMV (fp16 weights from SMEM) + cell update; warp wid = unit j
        {
            const int ch = sm->schars[t];
            const int j  = r * 32 + wid;
            float4 c0 = f4(&sm->ctxS[0 * 128 + lane * 4]);
            float4 c1 = f4(&sm->ctxS[1 * 128 + lane * 4]);
            float4 c2 = f4(&sm->ctxS[2 * 128 + lane * 4]);
            float4 c3 = f4(&sm->ctxS[3 * 128 + lane * 4]);
            float ag[3];
            #pragma unroll
            for (int g = 0; g < 3; g++) {
                const __half* wr = &sm->wihS[(g * 32 + wid) * 512 + lane * 4];
                float4 w0 = ldsh4(wr);
                float4 w1 = ldsh4(wr + 128);
                float4 w2 = ldsh4(wr + 256);
                float4 w3 = ldsh4(wr + 384);
                float a = w0.x * c0.x + w0.y * c0.y + w0.z * c0.z + w0.w * c0.w;
                a += w1.x * c1.x + w1.y * c1.y + w1.z * c1.z + w1.w * c1.w;
                a += w2.x * c2.x + w2.y * c2.y + w2.z * c2.z + w2.w * c2.w;
                a += w3.x * c3.x + w3.y * c3.y + w3.z * c3.z + w3.w * c3.w;
                ag[g] = a;
            }
            #pragma unroll
            for (int o = 16; o > 0; o >>= 1) {
                ag[0] += __shfl_xor_sync(0xffffffffu, ag[0], o);
                ag[1] += __shfl_xor_sync(0xffffffffu, ag[1], o);
                ag[2] += __shfl_xor_sync(0xffffffffu, ag[2], o);
            }
            float hnew = 0.f;
            if (lane == 0) {
                float inv = __fdividef(1.f, sm->ctxS[512]);
                float ir  = ag[0] * inv + g_wihEB[(0 * HID + j) * 32 + ch];
                float iz  = ag[1] * inv + g_wihEB[(1 * HID + j) * 32 + ch];
                float in_ = ag[2] * inv + g_wihEB[(2 * HID + j) * 32 + ch];
                float hr = sm->gh[wid], hz = sm->gh[32 + wid], hn = sm->gh[64 + wid];
                float rg = sigmoidf_(ir + hr);
                float zg = sigmoidf_(iz + hz);
                float ng = tanh_acc(in_ + rg * hn);
                hnew = (1.f - zg) * ng + zg * sm->hid[cur][j];
            }
            hnew = __shfl_sync(0xffffffffu, hnew, 0);
            if (lane < RCL)
                st_dsm(mapa_u32(smem_u32(&sm->hid[nxt][j]), lane), hnew);
            if (lane == 0) sm->hloc[wid] = hnew;
        }
        __syncthreads();
        // pp_part: k-split over 16 warps, then combine
        if (tid < 512) {
            int half = tid >> 8;             // 0/1: k-range halves
            int chn  = tid & 255;
            float a = 0.f;
            #pragma unroll 8
            for (int k = half * 16; k < half * 16 + 16; k++)
                a += sm->hloc[k] * sm->h2hs[k * HID + chn];
            sm->pp2[half][chn] = a;
        }
        __syncthreads();
        if (tid < HID)
            sm->pp_part[tid] = sm->pp2[0][tid] + sm->pp2[1][tid];
        CLUSTER_SYNC();   // S2: pp_part + hid[nxt] ready for next step
    }

    CLUSTER_SYNC();   // exit safety
}

// ---------------- launch ----------------
extern "C" void kernel_launch(void* const* d_in, const int* in_sizes, int n_in,
                              void* d_out, int out_size) {
    const float* fea       = (const float*)d_in[0];
    const int*   structure = (const int*)  d_in[1];
    const float* i2h_w     = (const float*)d_in[2];
    const float* h2h_w     = (const float*)d_in[3];
    const float* h2h_b     = (const float*)d_in[4];
    const float* score_w   = (const float*)d_in[5];
    const float* gru_wih   = (const float*)d_in[6];
    const float* gru_bih   = (const float*)d_in[7];
    const float* gru_whh   = (const float*)d_in[8];
    const float* gru_bhh   = (const float*)d_in[9];
    const float* sg1_w     = (const float*)d_in[10];
    const float* sg1_b     = (const float*)d_in[11];
    const float* sg2_w     = (const float*)d_in[12];
    const float* sg2_b     = (const float*)d_in[13];
    const float* lg1_w     = (const float*)d_in[14];
    const float* lg1_b     = (const float*)d_in[15];
    const float* lg2_w     = (const float*)d_in[16];
    const float* lg2_b     = (const float*)d_in[17];
    float* out = (float*)d_out;

    prep_kernel<<<OUTW + CC + HID + 3 * HID, HID>>>(
        i2h_w, h2h_w, gru_wih, gru_bih, gru_whh,
        sg1_w, sg1_b, sg2_w, sg2_b, lg1_w, lg1_b, lg2_w, lg2_b);

    cudaFuncSetAttribute(sla_kernel, cudaFuncAttributeMaxDynamicSharedMemorySize,
                         (int)sizeof(Smem));
    sla_kernel<<<BB * RCL, NTHR, sizeof(Smem)>>>(
        fea, structure, h2h_b, score_w, gru_bhh, out);
}

// round 13
// speedup vs baseline: 1.0133x; 1.0133x over previous
#include <cuda_runtime.h>
#include <cuda_fp16.h>
#include <cstdint>

#define BB    16
#define CC    512
#define NPOS  400
#define HID   256
#define NEMB  30
#define TT    201
#define OUTW  38
#define RCL   8
#define NLOC  50
#define NTHR  1024
#define FSTR2 520       // padded feat row stride (halves)

// ---------------- device scratch ----------------
__device__ float  g_i2h4[CC * HID];      // [c/4][h][4] interleaved fp32
__device__ float  g_Wcomb[OUTW * HID];   // fused output heads
__device__ float  g_bcomb[OUTW];
__device__ float  g_h2hT[HID * HID];     // h2h transposed: [j][i]
__device__ __half g_wihH[3 * HID * 512]; // wih ctx part, fp16
__device__ float  g_wihEB[3 * HID * 32]; // wih emb cols + bih folded, fp32
__device__ __half g_whhH[3 * HID * HID]; // whh, fp16

// ---------------- helpers ----------------
__device__ __forceinline__ uint32_t smem_u32(const void* p) {
    return (uint32_t)__cvta_generic_to_shared(p);
}
__device__ __forceinline__ uint32_t mapa_u32(uint32_t addr, uint32_t rank) {
    uint32_t r;
    asm("mapa.shared::cluster.u32 %0, %1, %2;" : "=r"(r) : "r"(addr), "r"(rank));
    return r;
}
__device__ __forceinline__ float ld_dsm(uint32_t a) {
    float v;
    asm volatile("ld.shared::cluster.f32 %0, [%1];" : "=f"(v) : "r"(a));
    return v;
}
__device__ __forceinline__ float2 ld_dsm_v2(uint32_t a) {
    float2 v;
    asm volatile("ld.shared::cluster.v2.f32 {%0, %1}, [%2];"
                 : "=f"(v.x), "=f"(v.y) : "r"(a));
    return v;
}
__device__ __forceinline__ void st_dsm(uint32_t a, float v) {
    asm volatile("st.shared::cluster.f32 [%0], %1;" :: "r"(a), "f"(v));
}
#define CLUSTER_SYNC() do { \
    asm volatile("barrier.cluster.arrive.aligned;" ::: "memory"); \
    asm volatile("barrier.cluster.wait.aligned;"   ::: "memory"); } while (0)
#define BAR1_768() asm volatile("bar.sync 1, 768;" ::: "memory")

__device__ __forceinline__ float sigmoidf_(float x) {
    return __fdividef(1.f, 1.f + __expf(-x));
}
__device__ __forceinline__ float tanh_acc(float x) {
    float cx = fminf(fmaxf(x, -15.f), 15.f);
    float e = __expf(2.f * cx);
    return __fdividef(e - 1.f, e + 1.f);
}
__device__ __forceinline__ __half2 tanh2(__half2 x) {   // HW f16x2 tanh
    uint32_t u = *reinterpret_cast<uint32_t*>(&x);
    asm("tanh.approx.f16x2 %0, %0;" : "+r"(u));
    return *reinterpret_cast<__half2*>(&u);
}
__device__ __forceinline__ float4 f4(const float* p) { return *(const float4*)p; }
__device__ __forceinline__ float2 f2(const float* p) { return *(const float2*)p; }
__device__ __forceinline__ float4 ldsh4(const __half* p) {   // 4 halves -> 4 floats
    uint2 u = *reinterpret_cast<const uint2*>(p);
    float2 a = __half22float2(*reinterpret_cast<half2*>(&u.x));
    float2 b = __half22float2(*reinterpret_cast<half2*>(&u.y));
    return make_float4(a.x, a.y, b.x, b.y);
}

// ---------------- prep kernel ----------------
__global__ void prep_kernel(const float* __restrict__ i2h, const float* __restrict__ h2h_w,
                            const float* __restrict__ wih, const float* __restrict__ bih,
                            const float* __restrict__ whh,
                            const float* __restrict__ sg1w, const float* __restrict__ sg1b,
                            const float* __restrict__ sg2w, const float* __restrict__ sg2b,
                            const float* __restrict__ lg1w, const float* __restrict__ lg1b,
                            const float* __restrict__ lg2w, const float* __restrict__ lg2b) {
    int blk = blockIdx.x, tid = threadIdx.x;
    if (blk < OUTW) {
        const float *W2, *W1, *b1, *b2; int row;
        if (blk < NEMB) { row = blk;        W2 = sg2w; W1 = sg1w; b1 = sg1b; b2 = sg2b; }
        else            { row = blk - NEMB; W2 = lg2w; W1 = lg1w; b1 = lg1b; b2 = lg2b; }
        float acc = 0.f;
        for (int k = 0; k < HID; k++) acc += W2[row * HID + k] * W1[k * HID + tid];
        g_Wcomb[blk * HID + tid] = acc;
        __shared__ float red[HID];
        red[tid] = W2[row * HID + tid] * b1[tid];
        __syncthreads();
        for (int s = HID / 2; s > 0; s >>= 1) {
            if (tid < s) red[tid] += red[tid + s];
            __syncthreads();
        }
        if (tid == 0) g_bcomb[blk] = red[0] + b2[row];
    } else if (blk < OUTW + CC) {
        int c = blk - OUTW;
        g_i2h4[(c >> 2) * HID * 4 + tid * 4 + (c & 3)] = i2h[tid * CC + c];
    } else if (blk < OUTW + CC + HID) {
        int j = blk - OUTW - CC;
        g_h2hT[j * HID + tid] = h2h_w[tid * HID + j];
    } else {
        int m = blk - OUTW - CC - HID;           // 0..767
        for (int c = tid; c < 512; c += HID)
            g_wihH[m * 512 + c] = __float2half_rn(wih[m * 542 + c]);
        if (tid < NEMB)
            g_wihEB[m * 32 + tid] = wih[m * 542 + 512 + tid] + bih[m];
        else if (tid < 32)
            g_wihEB[m * 32 + tid] = 0.f;
        g_whhH[m * HID + tid] = __float2half_rn(whh[m * HID + tid]);
    }
}

// ---------------- shared memory ----------------
struct __align__(16) Smem {
    __half  featH[NLOC * FSTR2]; // local feat slice, fp16  (52000 B)
    __half  hproj[NLOC * HID];   // i2h(feat) slice, fp16   (25600 B)
    __half  wihS[96 * 512];      // GRU wih slice, fp16     (98304 B)
    float   h2hs[32 * HID];      // h2hT slice, fp32        (32768 B)
    float   pp[HID];
    float   pp_part[HID];
    __half2 pctxI[512];          // interleaved ctx partials: [2c]=rows0-24, [2c+1]=rows25-49
    float   ctxS[516];           // reduced ctx fp32 (+ expsum at [512])
    float   h2hb[HID];
    float   hid[2][HID];
    float   gh[96];
    float   hloc[32];
    float   wexp[64];
    float   esloc;               // local expsum
    int     schars[224];
    float   pad[3];
};

// ---------------- main persistent cluster kernel ----------------
__global__ void __launch_bounds__(NTHR, 1) __cluster_dims__(RCL, 1, 1)
sla_kernel(const float* __restrict__ fea, const int* __restrict__ structure,
           const float* __restrict__ h2h_b, const float* __restrict__ score_w,
           const float* __restrict__ bhh,
           float* __restrict__ out) {
    extern __shared__ char smem_raw[];
    Smem* sm = (Smem*)smem_raw;
    const int tid  = threadIdx.x;
    const int lane = tid & 31;
    const int wid  = tid >> 5;
    const int b    = blockIdx.x >> 3;
    const int r    = blockIdx.x & 7;

    // ---- prologue: feat (fp16), wih slice (fp16), h2hT slice, biases ----
    {
        const float* fb = fea + (size_t)b * CC * NPOS;
        for (int idx = tid; idx < NLOC * CC; idx += NTHR) {
            int c  = idx / NLOC;
            int nl = idx - c * NLOC;
            sm->featH[nl * FSTR2 + c] = __float2half_rn(fb[c * NPOS + r * NLOC + nl]);
        }
        for (int i = tid; i < 96 * 512 / 8; i += NTHR) {
            int le = i * 8;
            int lr = le >> 9;                  // local row 0..95
            int cc = le & 511;
            int m  = (lr >> 5) * 256 + r * 32 + (lr & 31);
            reinterpret_cast<uint4*>(sm->wihS)[i] =
                reinterpret_cast<const uint4*>(g_wihH)[(m * 512 + cc) >> 3];
        }
        for (int i = tid; i < 32 * HID; i += NTHR)
            sm->h2hs[i] = g_h2hT[(size_t)(r * 32) * HID + i];
        for (int i = tid; i < HID; i += NTHR) {
            sm->h2hb[i]    = h2h_b[i];
            sm->hid[0][i]  = 0.f;
            sm->hid[1][i]  = 0.f;
            sm->pp_part[i] = 0.f;
        }
        if (tid < TT) sm->schars[tid] = structure[b * TT + tid];
        if (tid >= TT && tid < 224) sm->schars[tid] = 0;
    }
    __syncthreads();

    // ---- prologue: hproj[nl][h] = sum_c feat[nl][c] * i2h[h][c] (fp16 out) ----
    {
        int h  = tid & 255;
        int g  = tid >> 8;            // 0..3
        int n0 = g * 13;
        float acc[13];
        #pragma unroll
        for (int i = 0; i < 13; i++) acc[i] = 0.f;
        for (int cb = 0; cb < CC / 4; cb++) {
            float4 w = f4(&g_i2h4[cb * HID * 4 + h * 4]);
            #pragma unroll
            for (int i = 0; i < 13; i++) {
                int n = n0 + i;
                if (n < NLOC) {
                    float4 fv = ldsh4(&sm->featH[n * FSTR2 + cb * 4]);
                    acc[i] += fv.x * w.x + fv.y * w.y + fv.z * w.z + fv.w * w.w;
                }
            }
        }
        #pragma unroll
        for (int i = 0; i < 13; i++) {
            int n = n0 + i;
            if (n < NLOC) sm->hproj[n * HID + h] = __float2half_rn(acc[i]);
        }
    }

    // persistent score regs (half2) for attention warps
    __half2 sv2[4];
    if (wid < 24) {
        float4 s0 = f4(&score_w[lane * 8]);
        float4 s1 = f4(&score_w[lane * 8 + 4]);
        sv2[0] = __floats2half2_rn(s0.x, s0.y);
        sv2[1] = __floats2half2_rn(s0.z, s0.w);
        sv2[2] = __floats2half2_rn(s1.x, s1.y);
        sv2[3] = __floats2half2_rn(s1.z, s1.w);
    }
    CLUSTER_SYNC();

    // ---- decode loop (t == TT is the output-only epilogue) ----
    for (int t = 0; t <= TT; t++) {
        const int cur = t & 1, nxt = cur ^ 1;

        // ================= PHASE A =================
        if (wid >= 24) {
            float4 h0 = f4(&sm->hid[cur][lane * 8]);
            float4 h1 = f4(&sm->hid[cur][lane * 8 + 4]);
            if (t < TT) {
                // gh = whh @ h + bhh (12 gate-rows per warp), fp16 weights
                #pragma unroll 4
                for (int i = 0; i < 12; i++) {
                    int m2 = (wid - 24) * 12 + i;     // 0..95
                    int g  = m2 >> 5, u = m2 & 31;
                    const __half* wr = g_whhH + (size_t)(g * HID + r * 32 + u) * HID + lane * 8;
                    uint4 u4 = *reinterpret_cast<const uint4*>(wr);
                    half2* hh = reinterpret_cast<half2*>(&u4);
                    float2 w0 = __half22float2(hh[0]);
                    float2 w1 = __half22float2(hh[1]);
                    float2 w2 = __half22float2(hh[2]);
                    float2 w3 = __half22float2(hh[3]);
                    float a = w0.x * h0.x + w0.y * h0.y + w1.x * h0.z + w1.y * h0.w
                            + w2.x * h1.x + w2.y * h1.y + w3.x * h1.z + w3.y * h1.w;
                    #pragma unroll
                    for (int o = 16; o > 0; o >>= 1) a += __shfl_xor_sync(0xffffffffu, a, o);
                    if (lane == 0) sm->gh[m2] = a + bhh[g * HID + r * 32 + u];
                }
            }
            if (t > 0 && wid < 29) {
                int ow = r + 8 * (wid - 24);
                if (ow < OUTW) {
                    const float* wr = g_Wcomb + ow * HID + lane * 8;
                    float4 w0 = f4(wr), w1 = f4(wr + 4);
                    float a = w0.x * h0.x + w0.y * h0.y + w0.z * h0.z + w0.w * h0.w
                            + w1.x * h1.x + w1.y * h1.y + w1.z * h1.z + w1.w * h1.w;
                    #pragma unroll
                    for (int o = 16; o > 0; o >>= 1) a += __shfl_xor_sync(0xffffffffu, a, o);
                    if (lane == 0) {
                        a += g_bcomb[ow];
                        if (ow >= NEMB) a = sigmoidf_(a);
                        out[((size_t)b * TT + (t - 1)) * OUTW + ow] = a;
                    }
                }
            }
        } else if (t < TT) {
            // pp assemble: 128 threads, float2 remote pulls + bias
            if (tid < 128) {
                uint32_t base = smem_u32(&sm->pp_part[tid * 2]);
                float2 acc = f2(&sm->h2hb[tid * 2]);
                #pragma unroll
                for (int p = 0; p < RCL; p++) {
                    float2 v = ld_dsm_v2(mapa_u32(base, p));
                    acc.x += v.x; acc.y += v.y;
                }
                *(float2*)&sm->pp[tid * 2] = acc;
            }
            BAR1_768();
            // attention: rows 2*wid, 2*wid+1 (+48+wid for wid<2); f16x2 tanh + dot
            {
                float4 pv0 = f4(&sm->pp[lane * 8]);
                float4 pv1 = f4(&sm->pp[lane * 8 + 4]);
                __half2 pv2[4];
                pv2[0] = __floats2half2_rn(pv0.x, pv0.y);
                pv2[1] = __floats2half2_rn(pv0.z, pv0.w);
                pv2[2] = __floats2half2_rn(pv1.x, pv1.y);
                pv2[3] = __floats2half2_rn(pv1.z, pv1.w);
                int rows[3]; int nr = 2;
                rows[0] = 2 * wid; rows[1] = 2 * wid + 1;
                if (wid < 2) { rows[2] = 48 + wid; nr = 3; }
                for (int q = 0; q < nr; q++) {
                    int n = rows[q];
                    uint4 u = *reinterpret_cast<const uint4*>(&sm->hproj[n * HID + lane * 8]);
                    half2* hh = reinterpret_cast<half2*>(&u);
                    __half2 m0 = __hmul2(tanh2(__hadd2(hh[0], pv2[0])), sv2[0]);
                    __half2 m1 = __hmul2(tanh2(__hadd2(hh[1], pv2[1])), sv2[1]);
                    __half2 m2 = __hmul2(tanh2(__hadd2(hh[2], pv2[2])), sv2[2]);
                    __half2 m3 = __hmul2(tanh2(__hadd2(hh[3], pv2[3])), sv2[3]);
                    __half2 s2 = __hadd2(__hadd2(m0, m1), __hadd2(m2, m3));
                    float2 fs = __half22float2(s2);
                    float a = fs.x + fs.y;
                    #pragma unroll
                    for (int o = 16; o > 0; o >>= 1) a += __shfl_xor_sync(0xffffffffu, a, o);
                    if (lane == 0) sm->wexp[n] = __expf(a);
                }
            }
            BAR1_768();
            // partial context: warps 0-7 rows 0-24, warps 8-15 rows 25-49 (interleaved out)
            if (wid < 16) {
                int half = wid >> 3;             // 0 or 1
                int ch   = tid & 255;            // half2 channel
                const half2* fp2 = reinterpret_cast<const half2*>(sm->featH);
                float2 a = make_float2(0.f, 0.f);
                int n0g = half * 25;
                #pragma unroll 5
                for (int n = n0g; n < n0g + 25; n++) {
                    float w = sm->wexp[n];
                    float2 fv = __half22float2(fp2[n * (FSTR2 / 2) + ch]);
                    a.x += w * fv.x; a.y += w * fv.y;
                }
                sm->pctxI[2 * ch + half] = __floats2half2_rn(a.x, a.y);
            }
            if (wid == 16) {                 // local expsum -> esloc
                float v = (lane < 25) ? sm->wexp[lane] + sm->wexp[lane + 25] : 0.f;
                #pragma unroll
                for (int o = 16; o > 0; o >>= 1) v += __shfl_xor_sync(0xffffffffu, v, o);
                if (lane == 0) sm->esloc = v;
            }
        }
        if (t == TT) break;

        CLUSTER_SYNC();   // S1: pctxI/esloc + gh ready

        // ================= PHASE B =================
        // ctx all-reduce: 256 threads pull interleaved half2 pairs (v2) from 8 peers
        if (tid < 256) {
            uint32_t base = smem_u32(&sm->pctxI[tid * 2]);
            float ax = 0.f, ay = 0.f;
            #pragma unroll
            for (int p = 0; p < RCL; p++) {
                float2 raw = ld_dsm_v2(mapa_u32(base, p));
                float2 fa = __half22float2(*reinterpret_cast<half2*>(&raw.x));
                float2 fb = __half22float2(*reinterpret_cast<half2*>(&raw.y));
                ax += fa.x + fb.x; ay += fa.y + fb.y;
            }
            *(float2*)&sm->ctxS[tid * 2] = make_float2(ax, ay);
        }
        if (wid == 8) {              // expsum all-reduce
            float e = (lane < RCL) ? ld_dsm(mapa_u32(smem_u32(&sm->esloc), lane)) : 0.f;
            e += __shfl_xor_sync(0xffffffffu, e, 1);
            e += __shfl_xor_sync(0xffffffffu, e, 2);
            e += __shfl_xor_sync(0xffffffffu, e, 4);
            if (lane == 0) sm->ctxS[512] = e;
        }
        __syncthreads();

        // GRU input GEMV (fp16 weights from SMEM) + cell update; warp wid = unit j
        {
            const int ch = sm->schars[t];
            const int j  = r * 32 + wid;
            float4 c0 = f4(&sm->ctxS[0 * 128 + lane * 4]);
            float4 c1 = f4(&sm->ctxS[1 * 128 + lane * 4]);
            float4 c2 = f4(&sm->ctxS[2 * 128 + lane * 4]);
            float4 c3 = f4(&sm->ctxS[3 * 128 + lane * 4]);
            float ag[3];
            #pragma unroll
            for (int g = 0; g < 3; g++) {
                const __half* wr = &sm->wihS[(g * 32 + wid) * 512 + lane * 4];
                float4 w0 = ldsh4(wr);
                float4 w1 = ldsh4(wr + 128);
                float4 w2 = ldsh4(wr + 256);
                float4 w3 = ldsh4(wr + 384);
                float a = w0.x * c0.x + w0.y * c0.y + w0.z * c0.z + w0.w * c0.w;
                a += w1.x * c1.x + w1.y * c1.y + w1.z * c1.z + w1.w * c1.w;
                a += w2.x * c2.x + w2.y * c2.y + w2.z * c2.z + w2.w * c2.w;
                a += w3.x * c3.x + w3.y * c3.y + w3.z * c3.z + w3.w * c3.w;
                ag[g] = a;
            }
            #pragma unroll
            for (int o = 16; o > 0; o >>= 1) {
                ag[0] += __shfl_xor_sync(0xffffffffu, ag[0], o);
                ag[1] += __shfl_xor_sync(0xffffffffu, ag[1], o);
                ag[2] += __shfl_xor_sync(0xffffffffu, ag[2], o);
            }
            float hnew = 0.f;
            if (lane == 0) {
                float inv = __fdividef(1.f, sm->ctxS[512]);
                float ir  = ag[0] * inv + g_wihEB[(0 * HID + j) * 32 + ch];
                float iz  = ag[1] * inv + g_wihEB[(1 * HID + j) * 32 + ch];
                float in_ = ag[2] * inv + g_wihEB[(2 * HID + j) * 32 + ch];
                float hr = sm->gh[wid], hz = sm->gh[32 + wid], hn = sm->gh[64 + wid];
                float rg = sigmoidf_(ir + hr);
                float zg = sigmoidf_(iz + hz);
                float ng = tanh_acc(in_ + rg * hn);
                hnew = (1.f - zg) * ng + zg * sm->hid[cur][j];
            }
            hnew = __shfl_sync(0xffffffffu, hnew, 0);
            if (lane < RCL)
                st_dsm(mapa_u32(smem_u32(&sm->hid[nxt][j]), lane), hnew);
            if (lane == 0) sm->hloc[wid] = hnew;
        }
        __syncthreads();
        // column-partial of next prev_proj from SMEM-cached h2hT slice (8 warps)
        if (tid < HID) {
            float a = 0.f;
            #pragma unroll 8
            for (int k = 0; k < 32; k++)
                a += sm->hloc[k] * sm->h2hs[k * HID + tid];
            sm->pp_part[tid] = a;
        }
        CLUSTER_SYNC();   // S2: pp_part + hid[nxt] ready for next step
    }

    CLUSTER_SYNC();   // exit safety
}

// ---------------- launch ----------------
extern "C" void kernel_launch(void* const* d_in, const int* in_sizes, int n_in,
                              void* d_out, int out_size) {
    const float* fea       = (const float*)d_in[0];
    const int*   structure = (const int*)  d_in[1];
    const float* i2h_w     = (const float*)d_in[2];
    const float* h2h_w     = (const float*)d_in[3];
    const float* h2h_b     = (const float*)d_in[4];
    const float* score_w   = (const float*)d_in[5];
    const float* gru_wih   = (const float*)d_in[6];
    const float* gru_bih   = (const float*)d_in[7];
    const float* gru_whh   = (const float*)d_in[8];
    const float* gru_bhh   = (const float*)d_in[9];
    const float* sg1_w     = (const float*)d_in[10];
    const float* sg1_b     = (const float*)d_in[11];
    const float* sg2_w     = (const float*)d_in[12];
    const float* sg2_b     = (const float*)d_in[13];
    const float* lg1_w     = (const float*)d_in[14];
    const float* lg1_b     = (const float*)d_in[15];
    const float* lg2_w     = (const float*)d_in[16];
    const float* lg2_b     = (const float*)d_in[17];
    float* out = (float*)d_out;

    prep_kernel<<<OUTW + CC + HID + 3 * HID, HID>>>(
        i2h_w, h2h_w, gru_wih, gru_bih, gru_whh,
        sg1_w, sg1_b, sg2_w, sg2_b, lg1_w, lg1_b, lg2_w, lg2_b);

    cudaFuncSetAttribute(sla_kernel, cudaFuncAttributeMaxDynamicSharedMemorySize,
                         (int)sizeof(Smem));
    sla_kernel<<<BB * RCL, NTHR, sizeof(Smem)>>>(
        fea, structure, h2h_b, score_w, gru_bhh, out);
}

// round 15
// speedup vs baseline: 1.0854x; 1.0711x over previous
#include <cuda_runtime.h>
#include <cuda_fp16.h>
#include <cstdint>

#define BB    16
#define CC    512
#define NPOS  400
#define HID   256
#define NEMB  30
#define TT    201
#define OUTW  38
#define RCL   8
#define NLOC  50
#define NTHR  1024
#define FSTR2 520       // padded feat row stride (halves)

// ---------------- device scratch ----------------
__device__ float  g_i2h4[CC * HID];      // [c/4][h][4] interleaved fp32
__device__ float  g_Wcomb[OUTW * HID];   // fused output heads
__device__ float  g_bcomb[OUTW];
__device__ float  g_h2hT[HID * HID];     // h2h transposed: [j][i]
__device__ __half g_wihH[3 * HID * 512]; // wih ctx part, fp16
__device__ float  g_wihEB2[NEMB * 768];  // wih emb cols + bih, transposed: [ch][gate*256+unit]
__device__ __half g_whhH[3 * HID * HID]; // whh, fp16

// ---------------- helpers ----------------
__device__ __forceinline__ uint32_t smem_u32(const void* p) {
    return (uint32_t)__cvta_generic_to_shared(p);
}
__device__ __forceinline__ uint32_t mapa_u32(uint32_t addr, uint32_t rank) {
    uint32_t r;
    asm("mapa.shared::cluster.u32 %0, %1, %2;" : "=r"(r) : "r"(addr), "r"(rank));
    return r;
}
__device__ __forceinline__ float ld_dsm(uint32_t a) {
    float v;
    asm volatile("ld.shared::cluster.f32 %0, [%1];" : "=f"(v) : "r"(a));
    return v;
}
__device__ __forceinline__ uint32_t ld_dsm_u32(uint32_t a) {
    uint32_t v;
    asm volatile("ld.shared::cluster.b32 %0, [%1];" : "=r"(v) : "r"(a));
    return v;
}
__device__ __forceinline__ void st_dsm(uint32_t a, float v) {
    asm volatile("st.shared::cluster.f32 [%0], %1;" :: "r"(a), "f"(v));
}
#define CLUSTER_SYNC() do { \
    asm volatile("barrier.cluster.arrive.aligned;" ::: "memory"); \
    asm volatile("barrier.cluster.wait.aligned;"   ::: "memory"); } while (0)
#define BAR1_768() asm volatile("bar.sync 1, 768;" ::: "memory")

__device__ __forceinline__ float sigmoidf_(float x) {
    return __fdividef(1.f, 1.f + __expf(-x));
}
__device__ __forceinline__ float tanh_acc(float x) {
    float cx = fminf(fmaxf(x, -15.f), 15.f);
    float e = __expf(2.f * cx);
    return __fdividef(e - 1.f, e + 1.f);
}
__device__ __forceinline__ __half2 tanh2(__half2 x) {   // HW f16x2 tanh
    uint32_t u = *reinterpret_cast<uint32_t*>(&x);
    asm("tanh.approx.f16x2 %0, %0;" : "+r"(u));
    return *reinterpret_cast<__half2*>(&u);
}
__device__ __forceinline__ float4 f4(const float* p) { return *(const float4*)p; }
__device__ __forceinline__ float4 ldsh4(const __half* p) {   // 4 halves -> 4 floats
    uint2 u = *reinterpret_cast<const uint2*>(p);
    float2 a = __half22float2(*reinterpret_cast<half2*>(&u.x));
    float2 b = __half22float2(*reinterpret_cast<half2*>(&u.y));
    return make_float4(a.x, a.y, b.x, b.y);
}

// ---------------- prep kernel ----------------
__global__ void prep_kernel(const float* __restrict__ i2h, const float* __restrict__ h2h_w,
                            const float* __restrict__ wih, const float* __restrict__ bih,
                            const float* __restrict__ whh,
                            const float* __restrict__ sg1w, const float* __restrict__ sg1b,
                            const float* __restrict__ sg2w, const float* __restrict__ sg2b,
                            const float* __restrict__ lg1w, const float* __restrict__ lg1b,
                            const float* __restrict__ lg2w, const float* __restrict__ lg2b) {
    int blk = blockIdx.x, tid = threadIdx.x;
    if (blk < OUTW) {
        const float *W2, *W1, *b1, *b2; int row;
        if (blk < NEMB) { row = blk;        W2 = sg2w; W1 = sg1w; b1 = sg1b; b2 = sg2b; }
        else            { row = blk - NEMB; W2 = lg2w; W1 = lg1w; b1 = lg1b; b2 = lg2b; }
        float acc = 0.f;
        for (int k = 0; k < HID; k++) acc += W2[row * HID + k] * W1[k * HID + tid];
        g_Wcomb[blk * HID + tid] = acc;
        __shared__ float red[HID];
        red[tid] = W2[row * HID + tid] * b1[tid];
        __syncthreads();
        for (int s = HID / 2; s > 0; s >>= 1) {
            if (tid < s) red[tid] += red[tid + s];
            __syncthreads();
        }
        if (tid == 0) g_bcomb[blk] = red[0] + b2[row];
    } else if (blk < OUTW + CC) {
        int c = blk - OUTW;
        g_i2h4[(c >> 2) * HID * 4 + tid * 4 + (c & 3)] = i2h[tid * CC + c];
    } else if (blk < OUTW + CC + HID) {
        int j = blk - OUTW - CC;
        g_h2hT[j * HID + tid] = h2h_w[tid * HID + j];
    } else {
        int m = blk - OUTW - CC - HID;           // 0..767
        for (int c = tid; c < 512; c += HID)
            g_wihH[m * 512 + c] = __float2half_rn(wih[m * 542 + c]);
        if (tid < NEMB)
            g_wihEB2[tid * 768 + m] = wih[m * 542 + 512 + tid] + bih[m];
        g_whhH[m * HID + tid] = __float2half_rn(whh[m * HID + tid]);
    }
}

// ---------------- shared memory ----------------
struct __align__(16) Smem {
    __half  featH[NLOC * FSTR2]; // local feat slice, fp16  (52000 B)
    __half  hproj[NLOC * HID];   // i2h(feat) slice, fp16   (25600 B)
    __half  wihS[96 * 512];      // GRU wih slice, fp16     (98304 B)
    float   h2hs[32 * HID];      // h2hT slice, fp32        (32768 B)
    float   pp[HID];
    float   pp_part[HID];
    __half2 pctxH[256];          // partial ctx, half2       (1024 B)
    float   ctxS[516];           // reduced ctx fp32 (+ expsum at [512])
    float   h2hb[HID];
    float   hid[2][HID];
    float   gh[96];
    float   ebS[96];             // prefetched emb+bias row for ch(t)
    float   hloc[32];
    float   wexp[64];
    float   esloc;               // local expsum
    int     schars[224];
    float   pad[3];
};

// ---------------- main persistent cluster kernel ----------------
__global__ void __launch_bounds__(NTHR, 1) __cluster_dims__(RCL, 1, 1)
sla_kernel(const float* __restrict__ fea, const int* __restrict__ structure,
           const float* __restrict__ h2h_b, const float* __restrict__ score_w,
           const float* __restrict__ bhh,
           float* __restrict__ out) {
    extern __shared__ char smem_raw[];
    Smem* sm = (Smem*)smem_raw;
    const int tid  = threadIdx.x;
    const int lane = tid & 31;
    const int wid  = tid >> 5;
    const int b    = blockIdx.x >> 3;
    const int r    = blockIdx.x & 7;

    // ---- prologue: feat (fp16), wih slice (fp16), h2hT slice, biases ----
    {
        const float* fb = fea + (size_t)b * CC * NPOS;
        for (int idx = tid; idx < NLOC * CC; idx += NTHR) {
            int c  = idx / NLOC;
            int nl = idx - c * NLOC;
            sm->featH[nl * FSTR2 + c] = __float2half_rn(fb[c * NPOS + r * NLOC + nl]);
        }
        for (int i = tid; i < 96 * 512 / 8; i += NTHR) {
            int le = i * 8;
            int lr = le >> 9;                  // local row 0..95
            int cc = le & 511;
            int m  = (lr >> 5) * 256 + r * 32 + (lr & 31);
            reinterpret_cast<uint4*>(sm->wihS)[i] =
                reinterpret_cast<const uint4*>(g_wihH)[(m * 512 + cc) >> 3];
        }
        for (int i = tid; i < 32 * HID; i += NTHR)
            sm->h2hs[i] = g_h2hT[(size_t)(r * 32) * HID + i];
        for (int i = tid; i < HID; i += NTHR) {
            sm->h2hb[i]    = h2h_b[i];
            sm->hid[0][i]  = 0.f;
            sm->hid[1][i]  = 0.f;
            sm->pp_part[i] = 0.f;
        }
        if (tid < TT) sm->schars[tid] = structure[b * TT + tid];
        if (tid >= TT && tid < 224) sm->schars[tid] = 0;
    }
    __syncthreads();

    // ---- prologue: hproj[nl][h] = sum_c feat[nl][c] * i2h[h][c] (fp16 out) ----
    {
        int h  = tid & 255;
        int g  = tid >> 8;            // 0..3
        int n0 = g * 13;
        float acc[13];
        #pragma unroll
        for (int i = 0; i < 13; i++) acc[i] = 0.f;
        for (int cb = 0; cb < CC / 4; cb++) {
            float4 w = f4(&g_i2h4[cb * HID * 4 + h * 4]);
            #pragma unroll
            for (int i = 0; i < 13; i++) {
                int n = n0 + i;
                if (n < NLOC) {
                    float4 fv = ldsh4(&sm->featH[n * FSTR2 + cb * 4]);
                    acc[i] += fv.x * w.x + fv.y * w.y + fv.z * w.z + fv.w * w.w;
                }
            }
        }
        #pragma unroll
        for (int i = 0; i < 13; i++) {
            int n = n0 + i;
            if (n < NLOC) sm->hproj[n * HID + h] = __float2half_rn(acc[i]);
        }
    }

    // persistent score regs for attention warps
    float4 sv0 = make_float4(0.f, 0.f, 0.f, 0.f), sv1 = sv0;
    if (wid < 24) {
        sv0 = f4(&score_w[lane * 8]);
        sv1 = f4(&score_w[lane * 8 + 4]);
    }
    CLUSTER_SYNC();

    // ---- decode loop (t == TT is the output-only epilogue) ----
    for (int t = 0; t <= TT; t++) {
        const int cur = t & 1, nxt = cur ^ 1;

        // ================= PHASE A =================
        if (wid >= 24) {
            float4 h0 = f4(&sm->hid[cur][lane * 8]);
            float4 h1 = f4(&sm->hid[cur][lane * 8 + 4]);
            if (t < TT) {
                // gh = whh @ h + bhh (12 gate-rows per warp), fp16 weights
                #pragma unroll 4
                for (int i = 0; i < 12; i++) {
                    int m2 = (wid - 24) * 12 + i;     // 0..95
                    int g  = m2 >> 5, u = m2 & 31;
                    const __half* wr = g_whhH + (size_t)(g * HID + r * 32 + u) * HID + lane * 8;
                    uint4 u4 = *reinterpret_cast<const uint4*>(wr);
                    half2* hh = reinterpret_cast<half2*>(&u4);
                    float2 w0 = __half22float2(hh[0]);
                    float2 w1 = __half22float2(hh[1]);
                    float2 w2 = __half22float2(hh[2]);
                    float2 w3 = __half22float2(hh[3]);
                    float a = w0.x * h0.x + w0.y * h0.y + w1.x * h0.z + w1.y * h0.w
                            + w2.x * h1.x + w2.y * h1.y + w3.x * h1.z + w3.y * h1.w;
                    #pragma unroll
                    for (int o = 16; o > 0; o >>= 1) a += __shfl_xor_sync(0xffffffffu, a, o);
                    if (lane == 0) sm->gh[m2] = a + bhh[g * HID + r * 32 + u];
                }
            }
            if (t > 0 && wid < 29) {
                int ow = r + 8 * (wid - 24);
                if (ow < OUTW) {
                    const float* wr = g_Wcomb + ow * HID + lane * 8;
                    float4 w0 = f4(wr), w1 = f4(wr + 4);
                    float a = w0.x * h0.x + w0.y * h0.y + w0.z * h0.z + w0.w * h0.w
                            + w1.x * h1.x + w1.y * h1.y + w1.z * h1.z + w1.w * h1.w;
                    #pragma unroll
                    for (int o = 16; o > 0; o >>= 1) a += __shfl_xor_sync(0xffffffffu, a, o);
                    if (lane == 0) {
                        a += g_bcomb[ow];
                        if (ow >= NEMB) a = sigmoidf_(a);
                        out[((size_t)b * TT + (t - 1)) * OUTW + ow] = a;
                    }
                }
            }
        } else if (t < TT) {
            // assemble full prev_proj: sum of 8 column-partials + bias
            if (tid < HID) {
                uint32_t base = smem_u32(&sm->pp_part[tid]);
                float acc = sm->h2hb[tid];
                #pragma unroll
                for (int p = 0; p < RCL; p++) acc += ld_dsm(mapa_u32(base, p));
                sm->pp[tid] = acc;
            }
            BAR1_768();
            // attention: rows 2*wid, 2*wid+1 (interleaved reductions); +48+wid for wid<2
            {
                float4 pv0 = f4(&sm->pp[lane * 8]);
                float4 pv1 = f4(&sm->pp[lane * 8 + 4]);
                __half2 pv2[4];
                pv2[0] = __floats2half2_rn(pv0.x, pv0.y);
                pv2[1] = __floats2half2_rn(pv0.z, pv0.w);
                pv2[2] = __floats2half2_rn(pv1.x, pv1.y);
                pv2[3] = __floats2half2_rn(pv1.z, pv1.w);
                int n0r = 2 * wid, n1r = 2 * wid + 1;
                float a0, a1;
                {
                    uint4 u = *reinterpret_cast<const uint4*>(&sm->hproj[n0r * HID + lane * 8]);
                    half2* hh = reinterpret_cast<half2*>(&u);
                    float2 f0 = __half22float2(tanh2(__hadd2(hh[0], pv2[0])));
                    float2 f1 = __half22float2(tanh2(__hadd2(hh[1], pv2[1])));
                    float2 f2v = __half22float2(tanh2(__hadd2(hh[2], pv2[2])));
                    float2 f3 = __half22float2(tanh2(__hadd2(hh[3], pv2[3])));
                    a0 = f0.x * sv0.x + f0.y * sv0.y + f1.x * sv0.z + f1.y * sv0.w
                       + f2v.x * sv1.x + f2v.y * sv1.y + f3.x * sv1.z + f3.y * sv1.w;
                }
                {
                    uint4 u = *reinterpret_cast<const uint4*>(&sm->hproj[n1r * HID + lane * 8]);
                    half2* hh = reinterpret_cast<half2*>(&u);
                    float2 f0 = __half22float2(tanh2(__hadd2(hh[0], pv2[0])));
                    float2 f1 = __half22float2(tanh2(__hadd2(hh[1], pv2[1])));
                    float2 f2v = __half22float2(tanh2(__hadd2(hh[2], pv2[2])));
                    float2 f3 = __half22float2(tanh2(__hadd2(hh[3], pv2[3])));
                    a1 = f0.x * sv0.x + f0.y * sv0.y + f1.x * sv0.z + f1.y * sv0.w
                       + f2v.x * sv1.x + f2v.y * sv1.y + f3.x * sv1.z + f3.y * sv1.w;
                }
                #pragma unroll
                for (int o = 16; o > 0; o >>= 1) {
                    a0 += __shfl_xor_sync(0xffffffffu, a0, o);
                    a1 += __shfl_xor_sync(0xffffffffu, a1, o);
                }
                if (lane == 0) {
                    sm->wexp[n0r] = __expf(a0);
                    sm->wexp[n1r] = __expf(a1);
                }
                if (wid < 2) {
                    int n = 48 + wid;
                    uint4 u = *reinterpret_cast<const uint4*>(&sm->hproj[n * HID + lane * 8]);
                    half2* hh = reinterpret_cast<half2*>(&u);
                    float2 f0 = __half22float2(tanh2(__hadd2(hh[0], pv2[0])));
                    float2 f1 = __half22float2(tanh2(__hadd2(hh[1], pv2[1])));
                    float2 f2v = __half22float2(tanh2(__hadd2(hh[2], pv2[2])));
                    float2 f3 = __half22float2(tanh2(__hadd2(hh[3], pv2[3])));
                    float a = f0.x * sv0.x + f0.y * sv0.y + f1.x * sv0.z + f1.y * sv0.w
                            + f2v.x * sv1.x + f2v.y * sv1.y + f3.x * sv1.z + f3.y * sv1.w;
                    #pragma unroll
                    for (int o = 16; o > 0; o >>= 1) a += __shfl_xor_sync(0xffffffffu, a, o);
                    if (lane == 0) sm->wexp[n] = __expf(a);
                }
            }
            BAR1_768();
            if (wid < 8) {           // partial context, 256 threads x half2 (fp32 accum)
                const half2* fp2 = reinterpret_cast<const half2*>(sm->featH);
                float2 a = make_float2(0.f, 0.f);
                #pragma unroll 5
                for (int n = 0; n < NLOC; n++) {
                    float w = sm->wexp[n];
                    float2 fv = __half22float2(fp2[n * (FSTR2 / 2) + tid]);
                    a.x += w * fv.x; a.y += w * fv.y;
                }
                sm->pctxH[tid] = __floats2half2_rn(a.x, a.y);
            }
            if (wid == 16) {         // local expsum -> esloc
                float v = (lane < 25) ? sm->wexp[lane] + sm->wexp[lane + 25] : 0.f;
                #pragma unroll
                for (int o = 16; o > 0; o >>= 1) v += __shfl_xor_sync(0xffffffffu, v, o);
                if (lane == 0) sm->esloc = v;
            }
        }
        if (t == TT) break;

        const int ch = sm->schars[t];

        CLUSTER_SYNC();   // S1: pctxH/esloc + gh ready

        // ================= PHASE B =================
        // ctx all-reduce: 8 warps pull half2 partials from 8 peers, sum fp32
        if (tid < 256) {
            uint32_t base = smem_u32(&sm->pctxH[tid]);
            float ax = 0.f, ay = 0.f;
            #pragma unroll
            for (int p = 0; p < RCL; p++) {
                uint32_t raw = ld_dsm_u32(mapa_u32(base, p));
                float2 f = __half22float2(*reinterpret_cast<half2*>(&raw));
                ax += f.x; ay += f.y;
            }
            *(float2*)&sm->ctxS[tid * 2] = make_float2(ax, ay);
        }
        if (wid == 8) {              // expsum all-reduce
            float e = (lane < RCL) ? ld_dsm(mapa_u32(smem_u32(&sm->esloc), lane)) : 0.f;
            e += __shfl_xor_sync(0xffffffffu, e, 1);
            e += __shfl_xor_sync(0xffffffffu, e, 2);
            e += __shfl_xor_sync(0xffffffffu, e, 4);
            if (lane == 0) sm->ctxS[512] = e;
        }
        // warps 9-11: prefetch emb+bias row for ch(t) into SMEM (hides LDG latency)
        if (wid >= 9 && wid < 12) {
            int q = tid - 288;                 // 0..95
            sm->ebS[q] = g_wihEB2[ch * 768 + (q >> 5) * 256 + r * 32 + (q & 31)];
        }
        __syncthreads();

        // GRU input GEMV (fp16 weights from SMEM) + cell update; warp wid = unit j
        {
            const int j = r * 32 + wid;
            float4 c0 = f4(&sm->ctxS[0 * 128 + lane * 4]);
            float4 c1 = f4(&sm->ctxS[1 * 128 + lane * 4]);
            float4 c2 = f4(&sm->ctxS[2 * 128 + lane * 4]);
            float4 c3 = f4(&sm->ctxS[3 * 128 + lane * 4]);
            float ag[3];
            #pragma unroll
            for (int g = 0; g < 3; g++) {
                const __half* wr = &sm->wihS[(g * 32 + wid) * 512 + lane * 4];
                float4 w0 = ldsh4(wr);
                float4 w1 = ldsh4(wr + 128);
                float4 w2 = ldsh4(wr + 256);
                float4 w3 = ldsh4(wr + 384);
                float a = w0.x * c0.x + w0.y * c0.y + w0.z * c0.z + w0.w * c0.w;
                a += w1.x * c1.x + w1.y * c1.y + w1.z * c1.z + w1.w * c1.w;
                a += w2.x * c2.x + w2.y * c2.y + w2.z * c2.z + w2.w * c2.w;
                a += w3.x * c3.x + w3.y * c3.y + w3.z * c3.z + w3.w * c3.w;
                ag[g] = a;
            }
            #pragma unroll
            for (int o = 16; o > 0; o >>= 1) {
                ag[0] += __shfl_xor_sync(0xffffffffu, ag[0], o);
                ag[1] += __shfl_xor_sync(0xffffffffu, ag[1], o);
                ag[2] += __shfl_xor_sync(0xffffffffu, ag[2], o);
            }
            float hnew = 0.f;
            if (lane == 0) {
                float inv = __fdividef(1.f, sm->ctxS[512]);
                float ir  = ag[0] * inv + sm->ebS[wid];
                float iz  = ag[1] * inv + sm->ebS[32 + wid];
                float in_ = ag[2] * inv + sm->ebS[64 + wid];
                float hr = sm->gh[wid], hz = sm->gh[32 + wid], hn = sm->gh[64 + wid];
                float rg = sigmoidf_(ir + hr);
                float zg = sigmoidf_(iz + hz);
                float ng = tanh_acc(in_ + rg * hn);
                hnew = (1.f - zg) * ng + zg * sm->hid[cur][j];
            }
            hnew = __shfl_sync(0xffffffffu, hnew, 0);
            if (lane < RCL)
                st_dsm(mapa_u32(smem_u32(&sm->hid[nxt][j]), lane), hnew);
            if (lane == 0) sm->hloc[wid] = hnew;
        }
        __syncthreads();
        // column-partial of next prev_proj from SMEM-cached h2hT slice (8 warps)
        if (tid < HID) {
            float a = 0.f;
            #pragma unroll 8
            for (int k = 0; k < 32; k++)
                a += sm->hloc[k] * sm->h2hs[k * HID + tid];
            sm->pp_part[tid] = a;
        }
        CLUSTER_SYNC();   // S2: pp_part + hid[nxt] ready for next step
    }

    CLUSTER_SYNC();   // exit safety
}

// ---------------- launch ----------------
extern "C" void kernel_launch(void* const* d_in, const int* in_sizes, int n_in,
                              void* d_out, int out_size) {
    const float* fea       = (const float*)d_in[0];
    const int*   structure = (const int*)  d_in[1];
    const float* i2h_w     = (const float*)d_in[2];
    const float* h2h_w     = (const float*)d_in[3];
    const float* h2h_b     = (const float*)d_in[4];
    const float* score_w   = (const float*)d_in[5];
    const float* gru_wih   = (const float*)d_in[6];
    const float* gru_bih   = (const float*)d_in[7];
    const float* gru_whh   = (const float*)d_in[8];
    const float* gru_bhh   = (const float*)d_in[9];
    const float* sg1_w     = (const float*)d_in[10];
    const float* sg1_b     = (const float*)d_in[11];
    const float* sg2_w     = (const float*)d_in[12];
    const float* sg2_b     = (const float*)d_in[13];
    const float* lg1_w     = (const float*)d_in[14];
    const float* lg1_b     = (const float*)d_in[15];
    const float* lg2_w     = (const float*)d_in[16];
    const float* lg2_b     = (const float*)d_in[17];
    float* out = (float*)d_out;

    prep_kernel<<<OUTW + CC + HID + 3 * HID, HID>>>(
        i2h_w, h2h_w, gru_wih, gru_bih, gru_whh,
        sg1_w, sg1_b, sg2_w, sg2_b, lg1_w, lg1_b, lg2_w, lg2_b);

    cudaFuncSetAttribute(sla_kernel, cudaFuncAttributeMaxDynamicSharedMemorySize,
                         (int)sizeof(Smem));
    sla_kernel<<<BB * RCL, NTHR, sizeof(Smem)>>>(
        fea, structure, h2h_b, score_w, gru_bhh, out);
}